// round 14
// baseline (speedup 1.0000x reference)
#include <cuda_runtime.h>
#include <cstdint>

// ---------------------------------------------------------------------------
// Sparse CNN backbone, fp32, channel-pair SoA [C/2][n] float2.
// Full-tap convs, 128-thread CTAs, 2 rows/thread, SLICE out-channels per CTA;
// BN stats fused into conv epilogue (part[ch][tile]); BN fold inlined into
// elementwise consumers. ~32 warps/SM during convs.
// ---------------------------------------------------------------------------

#define MAXN2 80000
#define MAXN4 13824
#define MAXT 320   // max row tiles (256 rows each)
#define NB 64      // conv1 path only

__device__ float g_xc[MAXN2 * 32];
__device__ float g_z[MAXN2 * 32];
__device__ float g_zb1[MAXN2 * 32];   // conv1 partial B
__device__ float g_xt[MAXN2 * 32];
__device__ float g_y[MAXN4 * 64];
__device__ float g_part[64 * MAXT * 2];

typedef unsigned long long ull;

__device__ __forceinline__ ull pack2(float x) {
    ull r;
    asm("mov.b64 %0, {%1, %1};" : "=l"(r) : "f"(x));
    return r;
}
__device__ __forceinline__ void fma2(ull& d, ull a, ull b) {
    asm("fma.rn.f32x2 %0, %1, %2, %0;" : "+l"(d) : "l"(a), "l"(b));
}

// ---------------------------------------------------------------------------
// Full-tap conv: 128 threads, rows r0 = bx*256+tid, r1 = r0+128;
// blockIdx.y slices COUT by SLICE. STATS: per-(channel,tile) partials.
// ---------------------------------------------------------------------------
template <int CIN, int SLICE, bool STATS, int MAXB>
__global__ __launch_bounds__(128, MAXB) void conv_f(
    const float2* __restrict__ fT2, const float* __restrict__ W,
    const int* __restrict__ in_map, int n_in, int n_out, int COUT,
    float2* __restrict__ oT2, float* __restrict__ part) {
    extern __shared__ float sW[];  // [27][CIN][SLICE]
    const int tid = threadIdx.x;
    const int yoff = blockIdx.y * SLICE;
    constexpr int WV = SLICE / 4;

    for (int i = tid; i < 27 * CIN * WV; i += 128) {
        int r = i / WV, c4 = (i % WV) * 4;
        reinterpret_cast<float4*>(sW)[i] = *reinterpret_cast<const float4*>(
            W + (size_t)r * COUT + yoff + c4);
    }
    __syncthreads();

    const int r0 = blockIdx.x * 256 + tid;
    const int r1 = r0 + 128;
    const bool ok0 = r0 < n_out, ok1 = r1 < n_out;

    ull acc0[SLICE / 2], acc1[SLICE / 2];
#pragma unroll
    for (int i = 0; i < SLICE / 2; i++) { acc0[i] = 0ull; acc1[i] = 0ull; }

    int i0n = ok0 ? __ldg(&in_map[r0]) : n_in;
    int i1n = ok1 ? __ldg(&in_map[r1]) : n_in;

    for (int k = 0; k < 27; k++) {
        const int i0 = i0n, i1 = i1n;
        if (k + 1 < 27) {
            const int* mp = in_map + (size_t)(k + 1) * n_out;
            i0n = ok0 ? __ldg(&mp[r0]) : n_in;
            i1n = ok1 ? __ldg(&mp[r1]) : n_in;
        }
        const bool v0 = i0 < n_in, v1 = i1 < n_in;
        if (__ballot_sync(0xffffffffu, v0 | v1) == 0u) continue;

        const float* wk = sW + (size_t)k * CIN * SLICE;
        const float2 z2 = make_float2(0.f, 0.f);
#pragma unroll
        for (int q = 0; q < CIN / 8; q++) {
            float2 x0[4], x1[4];
#pragma unroll
            for (int j = 0; j < 4; j++) {
                const float2* colp = fT2 + (size_t)(q * 4 + j) * n_in;
                x0[j] = v0 ? __ldg(colp + i0) : z2;
                x1[j] = v1 ? __ldg(colp + i1) : z2;
            }
#pragma unroll
            for (int j = 0; j < 4; j++) {
                const int c0 = (q * 4 + j) * 2;
                ull a00 = pack2(x0[j].x), a01 = pack2(x0[j].y);
                ull a10 = pack2(x1[j].x), a11 = pack2(x1[j].y);
                const ulonglong2* w0 =
                    reinterpret_cast<const ulonglong2*>(wk + c0 * SLICE);
                const ulonglong2* w1 =
                    reinterpret_cast<const ulonglong2*>(wk + (c0 + 1) * SLICE);
#pragma unroll
                for (int p = 0; p < SLICE / 4; p++) {
                    ulonglong2 wa = w0[p], wb = w1[p];
                    fma2(acc0[2 * p], a00, wa.x);
                    fma2(acc0[2 * p + 1], a00, wa.y);
                    fma2(acc1[2 * p], a10, wa.x);
                    fma2(acc1[2 * p + 1], a10, wa.y);
                    fma2(acc0[2 * p], a01, wb.x);
                    fma2(acc0[2 * p + 1], a01, wb.y);
                    fma2(acc1[2 * p], a11, wb.x);
                    fma2(acc1[2 * p + 1], a11, wb.y);
                }
            }
        }
    }

    float v0s[SLICE], v1s[SLICE];
#pragma unroll
    for (int p = 0; p < SLICE / 2; p++) {
        float2 a = *reinterpret_cast<float2*>(&acc0[p]);
        v0s[2 * p] = a.x; v0s[2 * p + 1] = a.y;
        float2 b = *reinterpret_cast<float2*>(&acc1[p]);
        v1s[2 * p] = b.x; v1s[2 * p + 1] = b.y;
    }
    if (ok0) {
#pragma unroll
        for (int p = 0; p < SLICE / 2; p++)
            oT2[(size_t)(yoff / 2 + p) * n_out + r0] =
                *reinterpret_cast<float2*>(&acc0[p]);
    }
    if (ok1) {
#pragma unroll
        for (int p = 0; p < SLICE / 2; p++)
            oT2[(size_t)(yoff / 2 + p) * n_out + r1] =
                *reinterpret_cast<float2*>(&acc1[p]);
    }

    if (STATS) {
        __syncthreads();  // done with sW
        float* sv = sW;                  // 128*SLICE
        float* sq = sW + 128 * SLICE;    // 128*SLICE
#pragma unroll
        for (int s = 0; s < SLICE; s++) {
            // OOB rows have exact-zero accumulators
            sv[tid * SLICE + s] = v0s[s] + v1s[s];
            sq[tid * SLICE + s] = v0s[s] * v0s[s] + v1s[s] * v1s[s];
        }
        __syncthreads();
        constexpr int G = 128 / SLICE;
        const int c = tid % SLICE, g = tid / SLICE;
        float S = 0.f, Q = 0.f;
        for (int r = g; r < 128; r += G) {
            S += sv[r * SLICE + c];
            Q += sq[r * SLICE + c];
        }
        __syncthreads();
        sv[g * SLICE + c] = S;
        sq[g * SLICE + c] = Q;
        __syncthreads();
        if (tid < SLICE) {
            float S2 = 0.f, Q2 = 0.f;
#pragma unroll
            for (int r = 0; r < G; r++) {
                S2 += sv[r * SLICE + tid];
                Q2 += sq[r * SLICE + tid];
            }
            part[((size_t)(yoff + tid) * MAXT + blockIdx.x) * 2] = S2;
            part[((size_t)(yoff + tid) * MAXT + blockIdx.x) * 2 + 1] = Q2;
        }
    }
}

// ---------------------------------------------------------------------------
// First conv, 2-way K-split: CIN=4 (geo ++ col), COUT=32, K=125.
// ---------------------------------------------------------------------------
__global__ __launch_bounds__(256, 3) void conv1_k(
    const float* __restrict__ geo, const float* __restrict__ col,
    const float* __restrict__ W, const int* __restrict__ in_map, int n_in,
    int n_out, int KH, float2* __restrict__ oTa, float2* __restrict__ oTb) {
    extern __shared__ float sm[];
    const int tid = threadIdx.x;
    const int k0 = blockIdx.z ? KH : 0;
    const int k1 = blockIdx.z ? 125 : KH;
    const int taps = k1 - k0;

    for (int i = tid; i < taps * 32; i += 256)
        reinterpret_cast<float4*>(sm)[i] =
            reinterpret_cast<const float4*>(W + (size_t)k0 * 128)[i];
    __syncthreads();

    const int row = blockIdx.x * 256 + tid;
    if (row >= n_out) return;
    float2* __restrict__ oT2 = blockIdx.z ? oTb : oTa;

    ull acc[16];
#pragma unroll
    for (int i = 0; i < 16; i++) acc[i] = 0ull;

    int idxn = __ldg(&in_map[(size_t)k0 * n_out + row]);
    for (int k = k0; k < k1; k++) {
        int idx = idxn;
        if (k + 1 < k1) idxn = __ldg(&in_map[(size_t)(k + 1) * n_out + row]);
        if (idx >= n_in) continue;

        float fr[4];
        fr[0] = __ldg(&geo[idx]);
        fr[1] = __ldg(&col[(size_t)idx * 3]);
        fr[2] = __ldg(&col[(size_t)idx * 3 + 1]);
        fr[3] = __ldg(&col[(size_t)idx * 3 + 2]);
        const float* wk = sm + (k - k0) * 128;
#pragma unroll
        for (int c = 0; c < 4; c++) {
            ull a2 = pack2(fr[c]);
            const ulonglong2* wrow = reinterpret_cast<const ulonglong2*>(wk + c * 32);
#pragma unroll
            for (int p = 0; p < 8; p++) {
                ulonglong2 w = wrow[p];
                fma2(acc[2 * p], a2, w.x);
                fma2(acc[2 * p + 1], a2, w.y);
            }
        }
    }
#pragma unroll
    for (int p = 0; p < 16; p++)
        oT2[(size_t)p * n_out + row] = *reinterpret_cast<float2*>(&acc[p]);
}

// Warp-folded BN params for channel c over ntiles partials.
__device__ __forceinline__ void bn_fold(const float* part, int c, int ntiles,
                                        int n, const float* g, const float* b,
                                        int lane, float* sc_out, float* sh_out) {
    float s = 0.f, q = 0.f;
    for (int i = lane; i < ntiles; i += 32) {
        s += part[((size_t)c * MAXT + i) * 2];
        q += part[((size_t)c * MAXT + i) * 2 + 1];
    }
#pragma unroll
    for (int o = 16; o >= 1; o >>= 1) {
        s += __shfl_down_sync(0xffffffffu, s, o);
        q += __shfl_down_sync(0xffffffffu, q, o);
    }
    if (lane == 0) {
        float inv_n = 1.f / (float)n;
        float mu = s * inv_n;
        float var = q * inv_n - mu * mu;
        float sc = __ldg(&g[c]) * rsqrtf(var + 1e-5f);
        *sc_out = sc;
        *sh_out = __ldg(&b[c]) - mu * sc;
    }
}

// xt = relu(z*sc+sh); BN reduce folded. blockIdx.y = channel pair.
__global__ __launch_bounds__(256) void apply1(
    const float2* __restrict__ z, const float* __restrict__ part, int ntiles,
    const float* __restrict__ g, const float* __restrict__ bb,
    float2* __restrict__ out, int n) {
    __shared__ float sp[4];
    const int cp = blockIdx.y, tid = threadIdx.x;
    const int w = tid >> 5, lane = tid & 31;
    if (w < 2)
        bn_fold(part, 2 * cp + w, ntiles, n, g, bb, lane, &sp[2 * w], &sp[2 * w + 1]);
    __syncthreads();
    const float sc0 = sp[0], sh0 = sp[1], sc1 = sp[2], sh1 = sp[3];
    const size_t base = (size_t)cp * n;
    for (int i = blockIdx.x * 256 + tid; i < n; i += gridDim.x * 256) {
        float2 v = z[base + i];
        float2 o;
        o.x = fmaxf(v.x * sc0 + sh0, 0.f);
        o.y = fmaxf(v.y * sc1 + sh1, 0.f);
        out[base + i] = o;
    }
}

// out = relu(z*sc+sh + res); BN reduce folded.
__global__ __launch_bounds__(256) void res1(
    const float2* __restrict__ z, const float* __restrict__ part, int ntiles,
    const float* __restrict__ g, const float* __restrict__ bb,
    const float2* __restrict__ res, float2* __restrict__ out, int n) {
    __shared__ float sp[4];
    const int cp = blockIdx.y, tid = threadIdx.x;
    const int w = tid >> 5, lane = tid & 31;
    if (w < 2)
        bn_fold(part, 2 * cp + w, ntiles, n, g, bb, lane, &sp[2 * w], &sp[2 * w + 1]);
    __syncthreads();
    const float sc0 = sp[0], sh0 = sp[1], sc1 = sp[2], sh1 = sp[3];
    const size_t base = (size_t)cp * n;
    for (int i = blockIdx.x * 256 + tid; i < n; i += gridDim.x * 256) {
        float2 v = z[base + i], vr = res[base + i];
        float2 o;
        o.x = fmaxf(v.x * sc0 + sh0 + vr.x, 0.f);
        o.y = fmaxf(v.y * sc1 + sh1 + vr.y, 0.f);
        out[base + i] = o;
    }
}

// out = relu(a+b) (flat float4) — conv1 merge only.
__global__ __launch_bounds__(256) void comb_relu(
    const float4* __restrict__ a, const float4* __restrict__ b,
    float4* __restrict__ out, int total4) {
    for (int i = blockIdx.x * 256 + threadIdx.x; i < total4; i += gridDim.x * 256) {
        float4 va = a[i], vb = b[i];
        va.x = fmaxf(va.x + vb.x, 0.f);
        va.y = fmaxf(va.y + vb.y, 0.f);
        va.z = fmaxf(va.z + vb.z, 0.f);
        va.w = fmaxf(va.w + vb.w, 0.f);
        out[i] = va;
    }
}

// Final: relu(z*sc+sh + res) pair-SoA -> AoS d_out; BN reduce folded.
__global__ __launch_bounds__(256) void final1(
    const float* __restrict__ z, const float* __restrict__ part, int ntiles,
    const float* __restrict__ g, const float* __restrict__ bb,
    const float* __restrict__ res, float* __restrict__ out, int n) {
    __shared__ float t[64 * 65];
    __shared__ float spar[64], sshf[64], rs[256], rq[256];
    const int tid = threadIdx.x;
    {
        const int c = tid >> 2, r = tid & 3;
        float S = 0.f, Q = 0.f;
        for (int i = r; i < ntiles; i += 4) {
            S += part[((size_t)c * MAXT + i) * 2];
            Q += part[((size_t)c * MAXT + i) * 2 + 1];
        }
        rs[tid] = S;
        rq[tid] = Q;
    }
    __syncthreads();
    if (tid < 64) {
        float S = rs[4 * tid] + rs[4 * tid + 1] + rs[4 * tid + 2] + rs[4 * tid + 3];
        float Q = rq[4 * tid] + rq[4 * tid + 1] + rq[4 * tid + 2] + rq[4 * tid + 3];
        float inv_n = 1.f / (float)n;
        float mu = S * inv_n;
        float var = Q * inv_n - mu * mu;
        float sc = __ldg(&g[tid]) * rsqrtf(var + 1e-5f);
        spar[tid] = sc;
        sshf[tid] = __ldg(&bb[tid]) - mu * sc;
    }
    __syncthreads();

    const int R0 = blockIdx.x * 64;
    for (int i = tid; i < 4096; i += 256) {
        int c = i >> 6, r = i & 63;
        int row = R0 + r;
        float v = 0.f;
        if (row < n) {
            size_t o = ((size_t)(c >> 1) * n + row) * 2 + (c & 1);
            v = fmaxf(z[o] * spar[c] + sshf[c] + res[o], 0.f);
        }
        t[c * 65 + r] = v;
    }
    __syncthreads();
    for (int i = tid; i < 4096; i += 256) {
        int r = i >> 6, c = i & 63;
        int row = R0 + r;
        if (row < n) out[(size_t)row * 64 + c] = t[c * 65 + r];
    }
}

// ---------------------------------------------------------------------------
extern "C" void kernel_launch(void* const* d_in, const int* in_sizes, int n_in,
                              void* d_out, int out_size) {
    const float* x_geo = (const float*)d_in[0];
    const float* x_col = (const float*)d_in[1];
    const float* w0 = (const float*)d_in[2];
    const float* w_e1 = (const float*)d_in[3];
    const float* g_e1 = (const float*)d_in[4];
    const float* b_e1 = (const float*)d_in[5];
    const float* w2 = (const float*)d_in[6];
    const float* w_e2 = (const float*)d_in[7];
    const float* g_e2 = (const float*)d_in[8];
    const float* b_e2 = (const float*)d_in[9];
    const int* m1_in = (const int*)d_in[10];
    const int* m2_in = (const int*)d_in[12];
    const int* m3_in = (const int*)d_in[14];
    const int* m4_in = (const int*)d_in[16];

    const int N = in_sizes[0];
    const int n2 = in_sizes[10] / 125;
    const int n4 = in_sizes[14] / 27;

    float *xc, *z, *zb1, *xt, *yb, *part;
    cudaGetSymbolAddress((void**)&xc, g_xc);
    cudaGetSymbolAddress((void**)&z, g_z);
    cudaGetSymbolAddress((void**)&zb1, g_zb1);
    cudaGetSymbolAddress((void**)&xt, g_xt);
    cudaGetSymbolAddress((void**)&yb, g_y);
    cudaGetSymbolAddress((void**)&part, g_part);

    const int SM1 = 63 * 4 * 32 * 4;        // 32256
    const int SME1 = 27 * 32 * 8 * 4;       // 27648 (CIN32 SLICE8)
    const int SMC2 = 27 * 32 * 8 * 4;       // 27648 (CIN32 SLICE8)
    const int SME2 = 27 * 64 * 4 * 4;       // 27648 (CIN64 SLICE4)
    cudaFuncSetAttribute(conv1_k, cudaFuncAttributeMaxDynamicSharedMemorySize, SM1);
    cudaFuncSetAttribute(conv_f<32, 8, true, 6>, cudaFuncAttributeMaxDynamicSharedMemorySize, SME1);
    cudaFuncSetAttribute(conv_f<32, 8, false, 6>, cudaFuncAttributeMaxDynamicSharedMemorySize, SMC2);
    cudaFuncSetAttribute(conv_f<64, 4, true, 8>, cudaFuncAttributeMaxDynamicSharedMemorySize, SME2);

    const int tiles2 = (n2 + 255) / 256;
    const int tiles4 = (n4 + 255) / 256;
    const dim3 gc1((n2 + 255) / 256, 1, 2);
    const dim3 ge1(tiles2, 4);             // COUT32 / SLICE8
    const dim3 gc2(tiles4, 8);             // COUT64 / SLICE8
    const dim3 ge2(tiles4, 16);            // COUT64 / SLICE4
    const dim3 ga1((n2 + 2047) / 2048, 16);
    const dim3 ga2((n4 + 2047) / 2048, 32);
    const int t2 = n2 * 32 / 4;

    // conv1 (k5 s2, 4->32), ksplit 63/62 -> relu combine -> xc
    conv1_k<<<gc1, 256, SM1>>>(x_geo, x_col, w0, m1_in, N, n2, 63,
                               (float2*)z, (float2*)zb1);
    comb_relu<<<(t2 + 255) / 256 < 2048 ? (t2 + 255) / 256 : 2048, 256>>>(
        (const float4*)z, (const float4*)zb1, (float4*)xc, t2);

    // enc1: 2 BasicBlocks, 32ch (stats fused in conv)
    for (int i = 0; i < 2; i++) {
        const float* wA = w_e1 + (size_t)(i * 2 + 0) * 27 * 32 * 32;
        const float* wB = w_e1 + (size_t)(i * 2 + 1) * 27 * 32 * 32;
        conv_f<32, 8, true, 6><<<ge1, 128, SME1>>>(
            (const float2*)xc, wA, m2_in, n2, n2, 32, (float2*)z, part);
        apply1<<<ga1, 256>>>((const float2*)z, part, tiles2,
                             g_e1 + (size_t)(i * 2) * 32,
                             b_e1 + (size_t)(i * 2) * 32, (float2*)xt, n2);
        conv_f<32, 8, true, 6><<<ge1, 128, SME1>>>(
            (const float2*)xt, wB, m2_in, n2, n2, 32, (float2*)z, part);
        res1<<<ga1, 256>>>((const float2*)z, part, tiles2,
                           g_e1 + (size_t)(i * 2 + 1) * 32,
                           b_e1 + (size_t)(i * 2 + 1) * 32, (const float2*)xc,
                           (float2*)xc, n2);
    }

    // conv2 (32 -> 64 onto stride-4 coords) -> yb directly
    conv_f<32, 8, false, 6><<<gc2, 128, SMC2>>>(
        (const float2*)xc, w2, m3_in, n2, n4, 64, (float2*)yb, nullptr);

    // enc2: 2 BasicBlocks, 64ch
    for (int i = 0; i < 2; i++) {
        const float* wA = w_e2 + (size_t)(i * 2 + 0) * 27 * 64 * 64;
        const float* wB = w_e2 + (size_t)(i * 2 + 1) * 27 * 64 * 64;
        conv_f<64, 4, true, 8><<<ge2, 128, SME2>>>(
            (const float2*)yb, wA, m4_in, n4, n4, 64, (float2*)z, part);
        apply1<<<ga2, 256>>>((const float2*)z, part, tiles4,
                             g_e2 + (size_t)(i * 2) * 64,
                             b_e2 + (size_t)(i * 2) * 64, (float2*)xt, n4);
        conv_f<64, 4, true, 8><<<ge2, 128, SME2>>>(
            (const float2*)xt, wB, m4_in, n4, n4, 64, (float2*)z, part);
        if (i == 1) {
            final1<<<(n4 + 63) / 64, 256>>>(z, part, tiles4,
                                            g_e2 + (size_t)(i * 2 + 1) * 64,
                                            b_e2 + (size_t)(i * 2 + 1) * 64, yb,
                                            (float*)d_out, n4);
        } else {
            res1<<<ga2, 256>>>((const float2*)z, part, tiles4,
                               g_e2 + (size_t)(i * 2 + 1) * 64,
                               b_e2 + (size_t)(i * 2 + 1) * 64,
                               (const float2*)yb, (float2*)yb, n4);
        }
    }
}

// round 15
// speedup vs baseline: 1.3071x; 1.3071x over previous
#include <cuda_runtime.h>
#include <cstdint>

// ---------------------------------------------------------------------------
// Sparse CNN backbone, fp32, channel-QUAD SoA layout [C/4][n] float4.
// Convs: 2-way K-split, thread = 2 rows (t, t+256) x SLICE out-channels,
// weight LDS amortized over both rows, quad (LDG.128) gathers.
// ---------------------------------------------------------------------------

#define MAXN2 80000
#define MAXN4 13824
#define NB 64

__device__ float g_xc[MAXN2 * 32];
__device__ float g_za[MAXN2 * 32];
__device__ float g_zb[MAXN2 * 32];
__device__ float g_xt[MAXN2 * 32];
__device__ float g_y[MAXN4 * 64];
__device__ float g_part[64 * NB * 2];

typedef unsigned long long ull;

__device__ __forceinline__ ull pack2(float x) {
    ull r;
    asm("mov.b64 %0, {%1, %1};" : "=l"(r) : "f"(x));
    return r;
}
__device__ __forceinline__ void fma2(ull& d, ull a, ull b) {
    asm("fma.rn.f32x2 %0, %1, %2, %0;" : "+l"(d) : "l"(a), "l"(b));
}

// ---------------------------------------------------------------------------
// 2-row K-split conv, quad layout. fT4 [CIN/4][n_in] float4 -> oT4 partials.
// blockIdx.z: taps [0,KH)/[KH,K). blockIdx.y slices COUT by SLICE.
// ---------------------------------------------------------------------------
template <int CIN, int SLICE>
__global__ __launch_bounds__(256, 3) void conv_k(
    const float4* __restrict__ fT4, const float* __restrict__ W,
    const int* __restrict__ in_map, int n_in, int n_out, int COUT, int K,
    int KH, float4* __restrict__ oTa, float4* __restrict__ oTb) {
    extern __shared__ float sW[];  // [taps][CIN][SLICE]
    const int tid = threadIdx.x;
    const int yoff = blockIdx.y * SLICE;
    const int k0 = blockIdx.z ? KH : 0;
    const int k1 = blockIdx.z ? K : KH;
    const int taps = k1 - k0;
    constexpr int WV = SLICE / 4;

    for (int i = tid; i < taps * CIN * WV; i += 256) {
        int r = i / WV, c4 = (i % WV) * 4;
        reinterpret_cast<float4*>(sW)[i] = *reinterpret_cast<const float4*>(
            W + ((size_t)k0 * CIN + r) * COUT + yoff + c4);
    }
    __syncthreads();

    const int r0 = blockIdx.x * 512 + tid;
    const int r1 = r0 + 256;
    const bool ok0 = r0 < n_out, ok1 = r1 < n_out;
    if (!ok0) return;
    float4* __restrict__ oT4 = blockIdx.z ? oTb : oTa;

    ull acc0[SLICE / 2], acc1[SLICE / 2];
#pragma unroll
    for (int i = 0; i < SLICE / 2; i++) { acc0[i] = 0ull; acc1[i] = 0ull; }

    int i0n = __ldg(&in_map[(size_t)k0 * n_out + r0]);
    int i1n = ok1 ? __ldg(&in_map[(size_t)k0 * n_out + r1]) : n_in;

    const float4 z4 = make_float4(0.f, 0.f, 0.f, 0.f);

    for (int k = k0; k < k1; k++) {
        const int i0 = i0n, i1 = i1n;
        if (k + 1 < k1) {
            const int* mp = in_map + (size_t)(k + 1) * n_out;
            i0n = __ldg(&mp[r0]);
            i1n = ok1 ? __ldg(&mp[r1]) : n_in;
        }
        const bool v0 = i0 < n_in, v1 = i1 < n_in;
        if (__ballot_sync(0xffffffffu, v0 | v1) == 0u) continue;

        const float* wk = sW + (size_t)(k - k0) * CIN * SLICE;
#pragma unroll
        for (int q = 0; q < CIN / 8; q++) {  // 8 channels per batch, 2 LDG.128
            float4 A0 = v0 ? __ldg(fT4 + (size_t)(2 * q) * n_in + i0) : z4;
            float4 B0 = v0 ? __ldg(fT4 + (size_t)(2 * q + 1) * n_in + i0) : z4;
            float4 A1 = v1 ? __ldg(fT4 + (size_t)(2 * q) * n_in + i1) : z4;
            float4 B1 = v1 ? __ldg(fT4 + (size_t)(2 * q + 1) * n_in + i1) : z4;
            float e0[4] = {A0.x, A0.z, B0.x, B0.z};
            float o0[4] = {A0.y, A0.w, B0.y, B0.w};
            float e1[4] = {A1.x, A1.z, B1.x, B1.z};
            float o1[4] = {A1.y, A1.w, B1.y, B1.w};
#pragma unroll
            for (int j = 0; j < 4; j++) {
                const int c0 = q * 8 + 2 * j;
                ull a00 = pack2(e0[j]), a01 = pack2(o0[j]);
                ull a10 = pack2(e1[j]), a11 = pack2(o1[j]);
                const ulonglong2* w0 =
                    reinterpret_cast<const ulonglong2*>(wk + c0 * SLICE);
                const ulonglong2* w1 =
                    reinterpret_cast<const ulonglong2*>(wk + (c0 + 1) * SLICE);
#pragma unroll
                for (int p = 0; p < SLICE / 4; p++) {
                    ulonglong2 wa = w0[p], wb = w1[p];
                    fma2(acc0[2 * p], a00, wa.x);
                    fma2(acc0[2 * p + 1], a00, wa.y);
                    fma2(acc1[2 * p], a10, wa.x);
                    fma2(acc1[2 * p + 1], a10, wa.y);
                    fma2(acc0[2 * p], a01, wb.x);
                    fma2(acc0[2 * p + 1], a01, wb.y);
                    fma2(acc1[2 * p], a11, wb.x);
                    fma2(acc1[2 * p + 1], a11, wb.y);
                }
            }
        }
    }

#pragma unroll
    for (int p = 0; p < SLICE / 4; p++) {
        float2 lo = *reinterpret_cast<float2*>(&acc0[2 * p]);
        float2 hi = *reinterpret_cast<float2*>(&acc0[2 * p + 1]);
        oT4[(size_t)(yoff / 4 + p) * n_out + r0] =
            make_float4(lo.x, lo.y, hi.x, hi.y);
    }
    if (ok1) {
#pragma unroll
        for (int p = 0; p < SLICE / 4; p++) {
            float2 lo = *reinterpret_cast<float2*>(&acc1[2 * p]);
            float2 hi = *reinterpret_cast<float2*>(&acc1[2 * p + 1]);
            oT4[(size_t)(yoff / 4 + p) * n_out + r1] =
                make_float4(lo.x, lo.y, hi.x, hi.y);
        }
    }
}

// ---------------------------------------------------------------------------
// First conv, 2-way K-split: CIN=4 (geo ++ col), COUT=32, K=125, quad out.
// ---------------------------------------------------------------------------
__global__ __launch_bounds__(256, 3) void conv1_k(
    const float* __restrict__ geo, const float* __restrict__ col,
    const float* __restrict__ W, const int* __restrict__ in_map, int n_in,
    int n_out, int KH, float4* __restrict__ oTa, float4* __restrict__ oTb) {
    extern __shared__ float sm[];
    const int tid = threadIdx.x;
    const int k0 = blockIdx.z ? KH : 0;
    const int k1 = blockIdx.z ? 125 : KH;
    const int taps = k1 - k0;

    for (int i = tid; i < taps * 32; i += 256)
        reinterpret_cast<float4*>(sm)[i] =
            reinterpret_cast<const float4*>(W + (size_t)k0 * 128)[i];
    __syncthreads();

    const int row = blockIdx.x * 256 + tid;
    if (row >= n_out) return;
    float4* __restrict__ oT4 = blockIdx.z ? oTb : oTa;

    ull acc[16];
#pragma unroll
    for (int i = 0; i < 16; i++) acc[i] = 0ull;

    int idxn = __ldg(&in_map[(size_t)k0 * n_out + row]);
    for (int k = k0; k < k1; k++) {
        int idx = idxn;
        if (k + 1 < k1) idxn = __ldg(&in_map[(size_t)(k + 1) * n_out + row]);
        if (idx >= n_in) continue;

        float fr[4];
        fr[0] = __ldg(&geo[idx]);
        fr[1] = __ldg(&col[(size_t)idx * 3]);
        fr[2] = __ldg(&col[(size_t)idx * 3 + 1]);
        fr[3] = __ldg(&col[(size_t)idx * 3 + 2]);
        const float* wk = sm + (k - k0) * 128;
#pragma unroll
        for (int c = 0; c < 4; c++) {
            ull a2 = pack2(fr[c]);
            const ulonglong2* wrow = reinterpret_cast<const ulonglong2*>(wk + c * 32);
#pragma unroll
            for (int p = 0; p < 8; p++) {
                ulonglong2 w = wrow[p];
                fma2(acc[2 * p], a2, w.x);
                fma2(acc[2 * p + 1], a2, w.y);
            }
        }
    }
#pragma unroll
    for (int p = 0; p < 8; p++) {
        float2 lo = *reinterpret_cast<float2*>(&acc[2 * p]);
        float2 hi = *reinterpret_cast<float2*>(&acc[2 * p + 1]);
        oT4[(size_t)p * n_out + row] = make_float4(lo.x, lo.y, hi.x, hi.y);
    }
}

// ---------------------------------------------------------------------------
// Stats over (a+b), quad layout. blockIdx.y = channel quad.
// Deterministic: warp shuffle tree + fixed cross-warp fold.
// ---------------------------------------------------------------------------
__global__ __launch_bounds__(256) void stats4(
    const float4* __restrict__ a, const float4* __restrict__ b, int n,
    float* __restrict__ part) {
    __shared__ float smw[8][8];  // [warp][4 sums ++ 4 sumsqs]
    const int quad = blockIdx.y, tid = threadIdx.x;
    const int w = tid >> 5, lane = tid & 31;
    const size_t base = (size_t)quad * n;
    float s[4] = {0.f, 0.f, 0.f, 0.f}, q[4] = {0.f, 0.f, 0.f, 0.f};
    for (int i = blockIdx.x * 256 + tid; i < n; i += NB * 256) {
        float4 va = a[base + i], vb = b[base + i];
        float x0 = va.x + vb.x, x1 = va.y + vb.y;
        float x2 = va.z + vb.z, x3 = va.w + vb.w;
        s[0] += x0; q[0] += x0 * x0;
        s[1] += x1; q[1] += x1 * x1;
        s[2] += x2; q[2] += x2 * x2;
        s[3] += x3; q[3] += x3 * x3;
    }
#pragma unroll
    for (int o = 16; o >= 1; o >>= 1) {
#pragma unroll
        for (int v = 0; v < 4; v++) {
            s[v] += __shfl_down_sync(0xffffffffu, s[v], o);
            q[v] += __shfl_down_sync(0xffffffffu, q[v], o);
        }
    }
    if (lane == 0) {
#pragma unroll
        for (int v = 0; v < 4; v++) {
            smw[w][v] = s[v];
            smw[w][4 + v] = q[v];
        }
    }
    __syncthreads();
    if (tid < 8) {
        float acc = 0.f;
#pragma unroll
        for (int ww = 0; ww < 8; ww++) acc += smw[ww][tid];
        const int c = 4 * quad + (tid & 3);
        part[((size_t)c * NB + blockIdx.x) * 2 + (tid >> 2)] = acc;
    }
}

// Warp-folded BN params for channel c.
__device__ __forceinline__ void bn_fold(const float* part, int c, int n,
                                        const float* g, const float* b,
                                        int lane, float* sc_out, float* sh_out) {
    float s = part[((size_t)c * NB + lane) * 2] +
              part[((size_t)c * NB + lane + 32) * 2];
    float q = part[((size_t)c * NB + lane) * 2 + 1] +
              part[((size_t)c * NB + lane + 32) * 2 + 1];
#pragma unroll
    for (int o = 16; o >= 1; o >>= 1) {
        s += __shfl_down_sync(0xffffffffu, s, o);
        q += __shfl_down_sync(0xffffffffu, q, o);
    }
    if (lane == 0) {
        float inv_n = 1.f / (float)n;
        float mu = s * inv_n;
        float var = q * inv_n - mu * mu;
        float sc = __ldg(&g[c]) * rsqrtf(var + 1e-5f);
        *sc_out = sc;
        *sh_out = __ldg(&b[c]) - mu * sc;
    }
}

// xt = relu((a+b)*sc+sh), quad layout; BN reduce folded.
__global__ __launch_bounds__(256) void apply4(
    const float4* __restrict__ a, const float4* __restrict__ b,
    const float* __restrict__ part, const float* __restrict__ g,
    const float* __restrict__ bb, float4* __restrict__ out, int n) {
    __shared__ float sp[8];
    const int quad = blockIdx.y, tid = threadIdx.x;
    const int w = tid >> 5, lane = tid & 31;
    if (w < 4)
        bn_fold(part, 4 * quad + w, n, g, bb, lane, &sp[2 * w], &sp[2 * w + 1]);
    __syncthreads();
    const float sc0 = sp[0], sh0 = sp[1], sc1 = sp[2], sh1 = sp[3];
    const float sc2 = sp[4], sh2 = sp[5], sc3 = sp[6], sh3 = sp[7];
    const size_t base = (size_t)quad * n;
    for (int i = blockIdx.x * 256 + tid; i < n; i += gridDim.x * 256) {
        float4 va = a[base + i], vb = b[base + i];
        float4 o;
        o.x = fmaxf((va.x + vb.x) * sc0 + sh0, 0.f);
        o.y = fmaxf((va.y + vb.y) * sc1 + sh1, 0.f);
        o.z = fmaxf((va.z + vb.z) * sc2 + sh2, 0.f);
        o.w = fmaxf((va.w + vb.w) * sc3 + sh3, 0.f);
        out[base + i] = o;
    }
}

// out = relu((a+b)*sc+sh + res), quad layout; BN reduce folded.
__global__ __launch_bounds__(256) void res4(
    const float4* __restrict__ a, const float4* __restrict__ b,
    const float* __restrict__ part, const float* __restrict__ g,
    const float* __restrict__ bb, const float4* __restrict__ res,
    float4* __restrict__ out, int n) {
    __shared__ float sp[8];
    const int quad = blockIdx.y, tid = threadIdx.x;
    const int w = tid >> 5, lane = tid & 31;
    if (w < 4)
        bn_fold(part, 4 * quad + w, n, g, bb, lane, &sp[2 * w], &sp[2 * w + 1]);
    __syncthreads();
    const float sc0 = sp[0], sh0 = sp[1], sc1 = sp[2], sh1 = sp[3];
    const float sc2 = sp[4], sh2 = sp[5], sc3 = sp[6], sh3 = sp[7];
    const size_t base = (size_t)quad * n;
    for (int i = blockIdx.x * 256 + tid; i < n; i += gridDim.x * 256) {
        float4 va = a[base + i], vb = b[base + i], vr = res[base + i];
        float4 o;
        o.x = fmaxf((va.x + vb.x) * sc0 + sh0 + vr.x, 0.f);
        o.y = fmaxf((va.y + vb.y) * sc1 + sh1 + vr.y, 0.f);
        o.z = fmaxf((va.z + vb.z) * sc2 + sh2 + vr.z, 0.f);
        o.w = fmaxf((va.w + vb.w) * sc3 + sh3 + vr.w, 0.f);
        out[base + i] = o;
    }
}

// out = relu(a+b) (flat float4)
__global__ __launch_bounds__(256) void comb_relu(
    const float4* __restrict__ a, const float4* __restrict__ b,
    float4* __restrict__ out, int total4) {
    for (int i = blockIdx.x * 256 + threadIdx.x; i < total4; i += gridDim.x * 256) {
        float4 va = a[i], vb = b[i];
        va.x = fmaxf(va.x + vb.x, 0.f);
        va.y = fmaxf(va.y + vb.y, 0.f);
        va.z = fmaxf(va.z + vb.z, 0.f);
        va.w = fmaxf(va.w + vb.w, 0.f);
        out[i] = va;
    }
}

// out = a+b (flat float4)
__global__ __launch_bounds__(256) void comb_add(
    const float4* __restrict__ a, const float4* __restrict__ b,
    float4* __restrict__ out, int total4) {
    for (int i = blockIdx.x * 256 + threadIdx.x; i < total4; i += gridDim.x * 256) {
        float4 va = a[i], vb = b[i];
        va.x += vb.x; va.y += vb.y; va.z += vb.z; va.w += vb.w;
        out[i] = va;
    }
}

// Final: relu((za+zb)*sc+sh + res) quad-SoA -> AoS d_out; BN reduce folded.
__global__ __launch_bounds__(256) void final4(
    const float* __restrict__ za, const float* __restrict__ zb,
    const float* __restrict__ part, const float* __restrict__ g,
    const float* __restrict__ bb, const float* __restrict__ res,
    float* __restrict__ out, int n) {
    __shared__ float t[64 * 65];
    __shared__ float spar[64], sshf[64], rs[256], rq[256];
    const int tid = threadIdx.x;
    {
        const int c = tid >> 2, r = tid & 3;
        float S = 0.f, Q = 0.f;
#pragma unroll
        for (int i = 0; i < 16; i++) {
            S += part[((size_t)c * NB + r + 4 * i) * 2];
            Q += part[((size_t)c * NB + r + 4 * i) * 2 + 1];
        }
        rs[tid] = S;
        rq[tid] = Q;
    }
    __syncthreads();
    if (tid < 64) {
        float S = rs[4 * tid] + rs[4 * tid + 1] + rs[4 * tid + 2] + rs[4 * tid + 3];
        float Q = rq[4 * tid] + rq[4 * tid + 1] + rq[4 * tid + 2] + rq[4 * tid + 3];
        float inv_n = 1.f / (float)n;
        float mu = S * inv_n;
        float var = Q * inv_n - mu * mu;
        float sc = __ldg(&g[tid]) * rsqrtf(var + 1e-5f);
        spar[tid] = sc;
        sshf[tid] = __ldg(&bb[tid]) - mu * sc;
    }
    __syncthreads();

    const int R0 = blockIdx.x * 64;
    for (int i = tid; i < 4096; i += 256) {
        int c = i >> 6, r = i & 63;
        int row = R0 + r;
        float v = 0.f;
        if (row < n) {
            size_t o = ((size_t)(c >> 2) * n + row) * 4 + (c & 3);
            v = fmaxf((za[o] + zb[o]) * spar[c] + sshf[c] + res[o], 0.f);
        }
        t[c * 65 + r] = v;
    }
    __syncthreads();
    for (int i = tid; i < 4096; i += 256) {
        int r = i >> 6, c = i & 63;
        int row = R0 + r;
        if (row < n) out[(size_t)row * 64 + c] = t[c * 65 + r];
    }
}

// ---------------------------------------------------------------------------
extern "C" void kernel_launch(void* const* d_in, const int* in_sizes, int n_in,
                              void* d_out, int out_size) {
    const float* x_geo = (const float*)d_in[0];
    const float* x_col = (const float*)d_in[1];
    const float* w0 = (const float*)d_in[2];
    const float* w_e1 = (const float*)d_in[3];
    const float* g_e1 = (const float*)d_in[4];
    const float* b_e1 = (const float*)d_in[5];
    const float* w2 = (const float*)d_in[6];
    const float* w_e2 = (const float*)d_in[7];
    const float* g_e2 = (const float*)d_in[8];
    const float* b_e2 = (const float*)d_in[9];
    const int* m1_in = (const int*)d_in[10];
    const int* m2_in = (const int*)d_in[12];
    const int* m3_in = (const int*)d_in[14];
    const int* m4_in = (const int*)d_in[16];

    const int N = in_sizes[0];
    const int n2 = in_sizes[10] / 125;
    const int n4 = in_sizes[14] / 27;

    float *xc, *za, *zb, *xt, *yb, *part;
    cudaGetSymbolAddress((void**)&xc, g_xc);
    cudaGetSymbolAddress((void**)&za, g_za);
    cudaGetSymbolAddress((void**)&zb, g_zb);
    cudaGetSymbolAddress((void**)&xt, g_xt);
    cudaGetSymbolAddress((void**)&yb, g_y);
    cudaGetSymbolAddress((void**)&part, g_part);

    const int SM1 = 63 * 4 * 32 * 4;          // 32256
    const int SME1 = 14 * 32 * 16 * 4;        // 28672 (CIN32 SLICE16)
    const int SMC2 = 14 * 32 * 8 * 4;         // 14336 (CIN32 SLICE8)
    const int SME2 = 14 * 64 * 8 * 4;         // 28672 (CIN64 SLICE8)
    cudaFuncSetAttribute(conv1_k, cudaFuncAttributeMaxDynamicSharedMemorySize, SM1);
    cudaFuncSetAttribute(conv_k<32, 16>, cudaFuncAttributeMaxDynamicSharedMemorySize, SME1);
    cudaFuncSetAttribute(conv_k<32, 8>, cudaFuncAttributeMaxDynamicSharedMemorySize, SMC2);
    cudaFuncSetAttribute(conv_k<64, 8>, cudaFuncAttributeMaxDynamicSharedMemorySize, SME2);

    const int gx2 = (n2 + 255) / 256;
    const int hx2 = (n2 + 511) / 512;
    const int hx4 = (n4 + 511) / 512;
    const dim3 gc1(gx2, 1, 2);
    const dim3 ge1(hx2, 2, 2);                // COUT32 / SLICE16
    const dim3 gc2(hx4, 8, 2);                // COUT64 / SLICE8
    const dim3 ge2(hx4, 8, 2);
    const dim3 gs1(NB, 8), gs2(NB, 16);       // channel quads
    const dim3 ga1((n2 + 2047) / 2048, 8);
    const dim3 ga2((n4 + 2047) / 2048, 16);
    const int t2 = n2 * 32 / 4, t4 = n4 * 64 / 4;

    // conv1 (k5 s2, 4->32), ksplit 63/62 -> relu combine -> xc
    conv1_k<<<gc1, 256, SM1>>>(x_geo, x_col, w0, m1_in, N, n2, 63,
                               (float4*)za, (float4*)zb);
    comb_relu<<<(t2 + 255) / 256 < 2048 ? (t2 + 255) / 256 : 2048, 256>>>(
        (const float4*)za, (const float4*)zb, (float4*)xc, t2);

    // enc1: 2 BasicBlocks, 32ch; taps 14/13
    for (int i = 0; i < 2; i++) {
        const float* wA = w_e1 + (size_t)(i * 2 + 0) * 27 * 32 * 32;
        const float* wB = w_e1 + (size_t)(i * 2 + 1) * 27 * 32 * 32;
        conv_k<32, 16><<<ge1, 256, SME1>>>((const float4*)xc, wA, m2_in, n2, n2,
                                           32, 27, 14, (float4*)za, (float4*)zb);
        stats4<<<gs1, 256>>>((const float4*)za, (const float4*)zb, n2, part);
        apply4<<<ga1, 256>>>((const float4*)za, (const float4*)zb, part,
                             g_e1 + (size_t)(i * 2) * 32,
                             b_e1 + (size_t)(i * 2) * 32, (float4*)xt, n2);
        conv_k<32, 16><<<ge1, 256, SME1>>>((const float4*)xt, wB, m2_in, n2, n2,
                                           32, 27, 14, (float4*)za, (float4*)zb);
        stats4<<<gs1, 256>>>((const float4*)za, (const float4*)zb, n2, part);
        res4<<<ga1, 256>>>((const float4*)za, (const float4*)zb, part,
                           g_e1 + (size_t)(i * 2 + 1) * 32,
                           b_e1 + (size_t)(i * 2 + 1) * 32, (const float4*)xc,
                           (float4*)xc, n2);
    }

    // conv2 (32 -> 64 onto stride-4 coords), ksplit -> add -> yb
    conv_k<32, 8><<<gc2, 256, SMC2>>>((const float4*)xc, w2, m3_in, n2, n4, 64,
                                      27, 14, (float4*)za, (float4*)zb);
    comb_add<<<(t4 + 255) / 256 < 2048 ? (t4 + 255) / 256 : 2048, 256>>>(
        (const float4*)za, (const float4*)zb, (float4*)yb, t4);

    // enc2: 2 BasicBlocks, 64ch
    for (int i = 0; i < 2; i++) {
        const float* wA = w_e2 + (size_t)(i * 2 + 0) * 27 * 64 * 64;
        const float* wB = w_e2 + (size_t)(i * 2 + 1) * 27 * 64 * 64;
        conv_k<64, 8><<<ge2, 256, SME2>>>((const float4*)yb, wA, m4_in, n4, n4,
                                          64, 27, 14, (float4*)za, (float4*)zb);
        stats4<<<gs2, 256>>>((const float4*)za, (const float4*)zb, n4, part);
        apply4<<<ga2, 256>>>((const float4*)za, (const float4*)zb, part,
                             g_e2 + (size_t)(i * 2) * 64,
                             b_e2 + (size_t)(i * 2) * 64, (float4*)xt, n4);
        conv_k<64, 8><<<ge2, 256, SME2>>>((const float4*)xt, wB, m4_in, n4, n4,
                                          64, 27, 14, (float4*)za, (float4*)zb);
        stats4<<<gs2, 256>>>((const float4*)za, (const float4*)zb, n4, part);
        if (i == 1) {
            final4<<<(n4 + 63) / 64, 256>>>(za, zb, part,
                                            g_e2 + (size_t)(i * 2 + 1) * 64,
                                            b_e2 + (size_t)(i * 2 + 1) * 64, yb,
                                            (float*)d_out, n4);
        } else {
            res4<<<ga2, 256>>>((const float4*)za, (const float4*)zb, part,
                               g_e2 + (size_t)(i * 2 + 1) * 64,
                               b_e2 + (size_t)(i * 2 + 1) * 64,
                               (const float4*)yb, (float4*)yb, n4);
        }
    }
}